// round 1
// baseline (speedup 1.0000x reference)
#include <cuda_runtime.h>
#include <math.h>

// ---------------- problem constants ----------------
#define SEQ   10
#define WAY   5
#define SHOT  5
#define TT    45          // C(10,2)
#define D     2048        // OUT_DIM == IN_DIM
#define NQ    75
#define NS    25
#define NQT   3375        // NQ*TT
#define NST   1125        // NS*TT
#define QF    750         // NQ*SEQ query frames
#define SF    250         // NS*SEQ support frames

// itertools.combinations(range(10), 2) order
__constant__ int c_p0[TT] = {0,0,0,0,0,0,0,0,0, 1,1,1,1,1,1,1,1, 2,2,2,2,2,2,2,
                             3,3,3,3,3,3, 4,4,4,4,4, 5,5,5,5, 6,6,6, 7,7, 8};
__constant__ int c_p1[TT] = {1,2,3,4,5,6,7,8,9, 2,3,4,5,6,7,8,9, 3,4,5,6,7,8,9,
                             4,5,6,7,8,9, 5,6,7,8,9, 6,7,8,9, 7,8,9, 8,9, 9};

// ---------------- scratch (static device memory; no runtime allocs) ----------------
__device__ float g_EQ0[QF * D];       // query frames @ W[:, :2048]^T
__device__ float g_EQ1[QF * D];       // query frames @ W[:, 2048:]^T
__device__ float g_ES0[SF * D];
__device__ float g_ES1[SF * D];
__device__ float g_QE[NQT * D];       // q_embed
__device__ float g_SE[NST * D];       // support_all flattened [c*225 + s*45 + t]
__device__ float g_qn[NQT];           // squared norms
__device__ float g_sn[NST];
__device__ float g_DQ[NQT * NST];     // cdist(q_embed, support_all)
__device__ float g_SD[NST * NST];     // cdist(support_all, support_all)
__device__ float g_rowmax[WAY * NQT];
__device__ int   g_pos[WAY * NQT];
__device__ float g_ave[WAY * NQT];
__device__ int   g_record[WAY * NST];
__device__ float g_mask[WAY * NST];   // maskF[c][class(j)*225 + s2], 0 for own class
__device__ float g_msum[WAY];
__device__ float g_contrast[NQ * WAY];

// ---------------- init ----------------
__global__ void k_init() {
    int i = blockIdx.x * blockDim.x + threadIdx.x;
    if (i < WAY * NST) g_record[i] = 0;
    if (i < NQ * WAY)  g_contrast[i] = 0.f;
}

// ---------------- NT SGEMM: C[M,N] = A[M,K] * B[N,K]^T ----------------
// MODE 0: plain store.  MODE 1: C = sqrt(max(an[r]+bn[c]-2*acc, 0))
#define BM 128
#define BN 128
#define BK 16

template<int MODE>
__global__ void __launch_bounds__(256) sgemm_nt(
    const float* __restrict__ A, const float* __restrict__ B, float* __restrict__ C,
    int M, int N, int K, int lda, int ldb, int ldc,
    const float* __restrict__ an, const float* __restrict__ bn)
{
    __shared__ float As[BK][BM];
    __shared__ float Bs[BK][BN];
    int tid = threadIdx.x;
    int tx = tid & 15, ty = tid >> 4;
    int m0 = blockIdx.y * BM;
    int n0 = blockIdx.x * BN;

    float acc[8][8];
#pragma unroll
    for (int i = 0; i < 8; i++)
#pragma unroll
        for (int j = 0; j < 8; j++) acc[i][j] = 0.f;

    for (int kk = 0; kk < K; kk += BK) {
#pragma unroll
        for (int i = 0; i < 2; i++) {
            int e   = tid + i * 256;          // [0,512)
            int row = e >> 2;
            int k4  = (e & 3) * 4;
            float4 va = make_float4(0.f, 0.f, 0.f, 0.f);
            if (m0 + row < M)
                va = *(const float4*)(A + (size_t)(m0 + row) * lda + kk + k4);
            As[k4 + 0][row] = va.x; As[k4 + 1][row] = va.y;
            As[k4 + 2][row] = va.z; As[k4 + 3][row] = va.w;
            float4 vb = make_float4(0.f, 0.f, 0.f, 0.f);
            if (n0 + row < N)
                vb = *(const float4*)(B + (size_t)(n0 + row) * ldb + kk + k4);
            Bs[k4 + 0][row] = vb.x; Bs[k4 + 1][row] = vb.y;
            Bs[k4 + 2][row] = vb.z; Bs[k4 + 3][row] = vb.w;
        }
        __syncthreads();
#pragma unroll
        for (int k = 0; k < BK; k++) {
            float a[8], b[8];
            *(float4*)&a[0] = *(const float4*)&As[k][ty * 4];
            *(float4*)&a[4] = *(const float4*)&As[k][64 + ty * 4];
            *(float4*)&b[0] = *(const float4*)&Bs[k][tx * 4];
            *(float4*)&b[4] = *(const float4*)&Bs[k][64 + tx * 4];
#pragma unroll
            for (int i = 0; i < 8; i++)
#pragma unroll
                for (int j = 0; j < 8; j++) acc[i][j] += a[i] * b[j];
        }
        __syncthreads();
    }

#pragma unroll
    for (int i = 0; i < 8; i++) {
        int r = m0 + ((i < 4) ? (ty * 4 + i) : (64 + ty * 4 + i - 4));
        if (r >= M) continue;
#pragma unroll
        for (int j = 0; j < 8; j++) {
            int cc = n0 + ((j < 4) ? (tx * 4 + j) : (64 + tx * 4 + j - 4));
            if (cc >= N) continue;
            float v = acc[i][j];
            if (MODE == 1) {
                float sq = an[r] + bn[cc] - 2.f * v;
                v = sqrtf(fmaxf(sq, 0.f));
            }
            C[(size_t)r * ldc + cc] = v;
        }
    }
}

// ---------------- embedding build: relu(P[f0]+Q[f1]+b) + squared norm ----------------
__global__ void k_embed(const float* __restrict__ bias) {
    int row = blockIdx.x;         // [0, NQT+NST)
    int tid = threadIdx.x;        // 256
    const float *E0, *E1;
    float *dst, *nout;
    int f0, f1;
    if (row < NQT) {
        int n = row / TT, t = row % TT;
        f0 = n * SEQ + c_p0[t];
        f1 = n * SEQ + c_p1[t];
        E0 = g_EQ0; E1 = g_EQ1;
        dst = g_QE + (size_t)row * D; nout = &g_qn[row];
    } else {
        int si = row - NQT;
        int c = si / 225, r = si % 225;
        int s = r / TT, t = r % TT;
        int base = (c * SHOT + s) * SEQ;
        f0 = base + c_p0[t];
        f1 = base + c_p1[t];
        E0 = g_ES0; E1 = g_ES1;
        dst = g_SE + (size_t)si * D; nout = &g_sn[si];
    }
    const float4* a0 = (const float4*)(E0 + (size_t)f0 * D);
    const float4* a1 = (const float4*)(E1 + (size_t)f1 * D);
    const float4* bb = (const float4*)bias;
    float4* o4 = (float4*)dst;
    float nrm = 0.f;
    for (int v = tid; v < D / 4; v += 256) {
        float4 x = a0[v], y = a1[v], z = bb[v], r4;
        r4.x = fmaxf(x.x + y.x + z.x, 0.f);
        r4.y = fmaxf(x.y + y.y + z.y, 0.f);
        r4.z = fmaxf(x.z + y.z + z.z, 0.f);
        r4.w = fmaxf(x.w + y.w + z.w, 0.f);
        o4[v] = r4;
        nrm += r4.x * r4.x + r4.y * r4.y + r4.z * r4.z + r4.w * r4.w;
    }
    __shared__ float sred[256];
    sred[tid] = nrm; __syncthreads();
    for (int s = 128; s; s >>= 1) {
        if (tid < s) sred[tid] += sred[tid + s];
        __syncthreads();
    }
    if (tid == 0) *nout = sred[0];
}

// ---------------- per-(class, query-tuple) reductions: rowmax, argmax, ave ----------------
__global__ void k_classred() {
    int w = (blockIdx.x * blockDim.x + threadIdx.x) >> 5;
    int lane = threadIdx.x & 31;
    if (w >= WAY * NQT) return;
    int c = w / NQT, qi = w % NQT;
    const float* row = g_DQ + (size_t)qi * NST + c * 225;
    float best = -1.f; int bidx = 0;
    float g0 = -1.f, g1 = -1.f, g2 = -1.f, g3 = -1.f, g4 = -1.f;
    for (int j = lane; j < 225; j += 32) {
        float v = row[j];
        if (v > best) { best = v; bidx = j; }
        int s = j % 5;   // dist_class reshape: j = t'*5 + s'
        if      (s == 0) g0 = fmaxf(g0, v);
        else if (s == 1) g1 = fmaxf(g1, v);
        else if (s == 2) g2 = fmaxf(g2, v);
        else if (s == 3) g3 = fmaxf(g3, v);
        else             g4 = fmaxf(g4, v);
    }
#pragma unroll
    for (int off = 16; off; off >>= 1) {
        float ob = __shfl_down_sync(0xffffffff, best, off);
        int   oi = __shfl_down_sync(0xffffffff, bidx, off);
        if (ob > best || (ob == best && oi < bidx)) { best = ob; bidx = oi; }
        g0 = fmaxf(g0, __shfl_down_sync(0xffffffff, g0, off));
        g1 = fmaxf(g1, __shfl_down_sync(0xffffffff, g1, off));
        g2 = fmaxf(g2, __shfl_down_sync(0xffffffff, g2, off));
        g3 = fmaxf(g3, __shfl_down_sync(0xffffffff, g3, off));
        g4 = fmaxf(g4, __shfl_down_sync(0xffffffff, g4, off));
    }
    if (lane == 0) {
        g_rowmax[w] = best;
        g_pos[w]    = bidx;
        g_ave[w]    = (g0 + g1 + g2 + g3 + g4) * 0.2f;
    }
}

// ---------------- record accumulation over 3375 query tuples ----------------
__global__ void k_record() {
    int c = blockIdx.y;
    int tid = threadIdx.x;                 // 128
    __shared__ int srec[NST];
    for (int j = tid; j < NST; j += 128) srec[j] = 0;
    __syncthreads();
    int q0 = blockIdx.x * 125;             // 27 chunks * 125 = 3375
    for (int qi = q0; qi < q0 + 125; qi++) {
        int   p = g_pos[c * NQT + qi];
        float a = g_ave[c * NQT + qi];
        const float* row = g_SD + (size_t)(c * 225 + p) * NST;
        for (int j = tid; j < NST; j += 128)
            srec[j] += (row[j] > a) ? 1 : 0;
    }
    __syncthreads();
    for (int j = tid; j < NST; j += 128)
        atomicAdd(&g_record[c * NST + j], srec[j]);
}

// ---------------- threshold + mask + msum per class ----------------
__global__ void k_mask() {
    int c = blockIdx.x;
    int tid = threadIdx.x;                 // 256
    __shared__ float sred[256];
    __shared__ int   snz[256];
    __shared__ float s_thr;
    float msum_acc = 0.f;
    for (int m = 0; m < WAY; m++) {
        if (m == c) {
            if (tid < 225) g_mask[c * NST + m * 225 + tid] = 0.f;
            continue;
        }
        int rec = 0;
        if (tid < 225) rec = g_record[c * NST + m * 225 + tid];
        sred[tid] = (tid < 225) ? (float)rec : 0.f;
        snz[tid]  = (tid < 225 && rec != 0) ? 1 : 0;
        __syncthreads();
        for (int s = 128; s; s >>= 1) {
            if (tid < s) { sred[tid] += sred[tid + s]; snz[tid] += snz[tid + s]; }
            __syncthreads();
        }
        if (tid == 0) s_thr = sred[0] / fmaxf((float)snz[0], 1.f);
        __syncthreads();
        if (tid < 225) {
            float mk = ((float)rec < s_thr) ? 1.f : 0.f;
            g_mask[c * NST + m * 225 + tid] = mk;
            msum_acc += mk;
        }
        __syncthreads();
    }
    sred[tid] = msum_acc; __syncthreads();
    for (int s = 128; s; s >>= 1) {
        if (tid < s) sred[tid] += sred[tid + s];
        __syncthreads();
    }
    if (tid == 0) g_msum[c] = fmaxf(sred[0], 1.f);
}

// ---------------- masked mean over DQ columns -> contrast ----------------
__global__ void k_contrast() {
    int qi = blockIdx.x;
    int tid = threadIdx.x;                 // 128
    const float* row = g_DQ + (size_t)qi * NST;
    float a0 = 0.f, a1 = 0.f, a2 = 0.f, a3 = 0.f, a4 = 0.f;
    for (int j = tid; j < NST; j += 128) {
        float d = row[j];
        a0 += d * g_mask[0 * NST + j];
        a1 += d * g_mask[1 * NST + j];
        a2 += d * g_mask[2 * NST + j];
        a3 += d * g_mask[3 * NST + j];
        a4 += d * g_mask[4 * NST + j];
    }
    __shared__ float red[WAY][128];
    red[0][tid] = a0; red[1][tid] = a1; red[2][tid] = a2;
    red[3][tid] = a3; red[4][tid] = a4;
    __syncthreads();
    for (int s = 64; s; s >>= 1) {
        if (tid < s)
#pragma unroll
            for (int cc = 0; cc < WAY; cc++) red[cc][tid] += red[cc][tid + s];
        __syncthreads();
    }
    if (tid < WAY) {
        float val = red[tid][0] / g_msum[tid] * (1.f / (4.f * 45.f));
        atomicAdd(&g_contrast[(qi / TT) * WAY + tid], val);
    }
}

// ---------------- final outputs ----------------
__global__ void k_final(float* __restrict__ out, int out_size) {
    int idx = blockIdx.x * blockDim.x + threadIdx.x;
    if (idx >= NQ * WAY) return;
    int n = idx / WAY, c = idx % WAY;
    float s = 0.f;
    for (int t = 0; t < TT; t++) s += g_rowmax[c * NQT + n * TT + t];
    float dm = s * (1.f / 45.f);
    float ct = g_contrast[idx];
    float lg = dm / (ct + dm);
    if (idx < out_size) out[idx] = dm;
    if (NQ * WAY + idx < out_size) out[NQ * WAY + idx] = lg;
}

// ---------------- launch ----------------
extern "C" void kernel_launch(void* const* d_in, const int* in_sizes, int n_in,
                              void* d_out, int out_size) {
    const float* support = (const float*)d_in[0];   // [25,10,2048]
    const float* queries = (const float*)d_in[2];   // [75,10,2048]
    const float* W       = (const float*)d_in[3];   // [2048,4096]
    const float* bias    = (const float*)d_in[4];   // [2048]
    float* out = (float*)d_out;

    float *EQ0, *EQ1, *ES0, *ES1, *QE, *SE, *qn, *sn, *DQ, *SD;
    cudaGetSymbolAddress((void**)&EQ0, g_EQ0);
    cudaGetSymbolAddress((void**)&EQ1, g_EQ1);
    cudaGetSymbolAddress((void**)&ES0, g_ES0);
    cudaGetSymbolAddress((void**)&ES1, g_ES1);
    cudaGetSymbolAddress((void**)&QE,  g_QE);
    cudaGetSymbolAddress((void**)&SE,  g_SE);
    cudaGetSymbolAddress((void**)&qn,  g_qn);
    cudaGetSymbolAddress((void**)&sn,  g_sn);
    cudaGetSymbolAddress((void**)&DQ,  g_DQ);
    cudaGetSymbolAddress((void**)&SD,  g_SD);

    k_init<<<22, 256>>>();

    // per-frame half-projections: P = F @ W0^T, Q = F @ W1^T
    sgemm_nt<0><<<dim3(16, 6), 256>>>(queries, W,        EQ0, QF, D, D, D, 2 * D, D, nullptr, nullptr);
    sgemm_nt<0><<<dim3(16, 6), 256>>>(queries, W + D,    EQ1, QF, D, D, D, 2 * D, D, nullptr, nullptr);
    sgemm_nt<0><<<dim3(16, 2), 256>>>(support, W,        ES0, SF, D, D, D, 2 * D, D, nullptr, nullptr);
    sgemm_nt<0><<<dim3(16, 2), 256>>>(support, W + D,    ES1, SF, D, D, D, 2 * D, D, nullptr, nullptr);

    k_embed<<<NQT + NST, 256>>>(bias);

    // distance matrices (GEMM + sqrt epilogue)
    sgemm_nt<1><<<dim3(9, 27), 256>>>(QE, SE, DQ, NQT, NST, D, D, D, NST, qn, sn);
    sgemm_nt<1><<<dim3(9, 9),  256>>>(SE, SE, SD, NST, NST, D, D, D, NST, sn, sn);

    k_classred<<<2110, 256>>>();
    k_record<<<dim3(27, WAY), 128>>>();
    k_mask<<<WAY, 256>>>();
    k_contrast<<<NQT, 128>>>();
    k_final<<<2, 256>>>(out, out_size);
}

// round 2
// speedup vs baseline: 1.5531x; 1.5531x over previous
#include <cuda_runtime.h>
#include <math.h>

// ---------------- problem constants ----------------
#define SEQ   10
#define WAY   5
#define SHOT  5
#define TT    45          // C(10,2)
#define D     2048        // OUT_DIM == IN_DIM
#define NQ    75
#define NS    25
#define NQT   3375        // NQ*TT
#define NST   1125        // NS*TT
#define QF    750         // NQ*SEQ query frames
#define SF    250         // NS*SEQ support frames
#define NF    1000        // total frames

// itertools.combinations(range(10), 2) order
__constant__ int c_p0[TT] = {0,0,0,0,0,0,0,0,0, 1,1,1,1,1,1,1,1, 2,2,2,2,2,2,2,
                             3,3,3,3,3,3, 4,4,4,4,4, 5,5,5,5, 6,6,6, 7,7, 8};
__constant__ int c_p1[TT] = {1,2,3,4,5,6,7,8,9, 2,3,4,5,6,7,8,9, 3,4,5,6,7,8,9,
                             4,5,6,7,8,9, 5,6,7,8,9, 6,7,8,9, 7,8,9, 8,9, 9};

// ---------------- scratch (static device memory; no runtime allocs) ----------------
__device__ float g_EF[NF * 2 * D];    // per-frame projections: [frame][0:2048]=W0 half, [2048:4096]=W1 half
__device__ float g_QE[NQT * D];       // q_embed
__device__ float g_SE[NST * D];       // support_all flattened [c*225 + s*45 + t]
__device__ float g_qn[NQT];           // squared norms
__device__ float g_sn[NST];
__device__ float g_DQ[NQT * NST];     // cdist(q_embed, support_all)
__device__ float g_SD[NST * NST];     // cdist(support_all, support_all)
__device__ float g_rowmax[WAY * NQT];
__device__ int   g_pos[WAY * NQT];
__device__ float g_ave[WAY * NQT];
__device__ int   g_record[WAY * NST];
__device__ float g_mask[WAY * NST];
__device__ float g_msum[WAY];
__device__ float g_contrast[NQ * WAY];

typedef unsigned long long u64;

__device__ __forceinline__ u64 pk(float lo, float hi) {
    u64 r; asm("mov.b64 %0, {%1, %2};" : "=l"(r) : "f"(lo), "f"(hi)); return r;
}
__device__ __forceinline__ void ffma2(u64& d, u64 a, u64 b) {
    asm("fma.rn.f32x2 %0, %1, %2, %0;" : "+l"(d) : "l"(a), "l"(b));
}
__device__ __forceinline__ float2 upk(u64 v) {
    float2 f; asm("mov.b64 {%0, %1}, %2;" : "=f"(f.x), "=f"(f.y) : "l"(v)); return f;
}

// ---------------- init ----------------
__global__ void k_init() {
    int i = blockIdx.x * blockDim.x + threadIdx.x;
    if (i < WAY * NST) g_record[i] = 0;
    if (i < NQ * WAY)  g_contrast[i] = 0.f;
}

// ---------------- NT SGEMM with FFMA2 core: C[M,N] = A[M,K] * B[N,K]^T ----------------
// MODE 0: plain store.
// MODE 1: C = sqrt(max(an[r]+bn[c]-2*acc, 0))
// MODE 2: embedding fused mode: A rows 0..749 from A (queries), 750.. from A2 (support);
//         B row n -> W + (n&2047)*4096 + (n&2048); plain store.
#define BM 128
#define BN 128
#define BK 16

template<int MODE>
__global__ void __launch_bounds__(256) sgemm_nt(
    const float* __restrict__ A, const float* __restrict__ A2,
    const float* __restrict__ B, float* __restrict__ C,
    int M, int N, int K, int lda, int ldb, int ldc,
    const float* __restrict__ an, const float* __restrict__ bn)
{
    __shared__ float Ash[BK][BM];
    __shared__ float Bsh[BK][BN];
    int tid = threadIdx.x;
    int tx = tid & 15, ty = tid >> 4;
    int m0 = blockIdx.y * BM;
    int n0 = blockIdx.x * BN;

    u64 acc2[8][4];
#pragma unroll
    for (int i = 0; i < 8; i++)
#pragma unroll
        for (int j = 0; j < 4; j++) acc2[i][j] = 0ull;

    for (int kk = 0; kk < K; kk += BK) {
#pragma unroll
        for (int i = 0; i < 2; i++) {
            int e   = tid + i * 256;          // [0,512)
            int row = e >> 2;
            int k4  = (e & 3) * 4;
            // A tile
            int r = m0 + row;
            float4 va = make_float4(0.f, 0.f, 0.f, 0.f);
            if (r < M) {
                const float* arow;
                if (MODE == 2) arow = (r < QF) ? (A + (size_t)r * D) : (A2 + (size_t)(r - QF) * D);
                else           arow = A + (size_t)r * lda;
                va = *(const float4*)(arow + kk + k4);
            }
            Ash[k4 + 0][row] = va.x; Ash[k4 + 1][row] = va.y;
            Ash[k4 + 2][row] = va.z; Ash[k4 + 3][row] = va.w;
            // B tile
            int nr = n0 + row;
            float4 vb = make_float4(0.f, 0.f, 0.f, 0.f);
            if (nr < N) {
                const float* brow;
                if (MODE == 2) brow = B + (size_t)(nr & 2047) * 4096 + (nr & 2048);
                else           brow = B + (size_t)nr * ldb;
                vb = *(const float4*)(brow + kk + k4);
            }
            Bsh[k4 + 0][row] = vb.x; Bsh[k4 + 1][row] = vb.y;
            Bsh[k4 + 2][row] = vb.z; Bsh[k4 + 3][row] = vb.w;
        }
        __syncthreads();
#pragma unroll
        for (int k = 0; k < BK; k++) {
            float4 a0 = *(const float4*)&Ash[k][ty * 4];
            float4 a1 = *(const float4*)&Ash[k][64 + ty * 4];
            u64 aa[8];
            aa[0] = pk(a0.x, a0.x); aa[1] = pk(a0.y, a0.y);
            aa[2] = pk(a0.z, a0.z); aa[3] = pk(a0.w, a0.w);
            aa[4] = pk(a1.x, a1.x); aa[5] = pk(a1.y, a1.y);
            aa[6] = pk(a1.z, a1.z); aa[7] = pk(a1.w, a1.w);
            const u64* bp0 = (const u64*)&Bsh[k][tx * 4];
            const u64* bp1 = (const u64*)&Bsh[k][64 + tx * 4];
            u64 b2[4];
            b2[0] = bp0[0]; b2[1] = bp0[1];
            b2[2] = bp1[0]; b2[3] = bp1[1];
#pragma unroll
            for (int i = 0; i < 8; i++)
#pragma unroll
                for (int j = 0; j < 4; j++) ffma2(acc2[i][j], aa[i], b2[j]);
        }
        __syncthreads();
    }

#pragma unroll
    for (int i = 0; i < 8; i++) {
        int r = m0 + ((i < 4) ? (ty * 4 + i) : (64 + ty * 4 + i - 4));
        if (r >= M) continue;
        float anr = (MODE == 1) ? an[r] : 0.f;
#pragma unroll
        for (int j = 0; j < 4; j++) {
            int cc = n0 + ((j < 2) ? (tx * 4 + j * 2) : (64 + tx * 4 + (j - 2) * 2));
            float2 v2 = upk(acc2[i][j]);
            float v0 = v2.x, v1 = v2.y;
            if (MODE == 1) {
                v0 = sqrtf(fmaxf(anr + bn[cc]     - 2.f * v0, 0.f));
                v1 = sqrtf(fmaxf(anr + bn[cc + 1] - 2.f * v1, 0.f));
            }
            if (cc < N)     C[(size_t)r * ldc + cc]     = v0;
            if (cc + 1 < N) C[(size_t)r * ldc + cc + 1] = v1;
        }
    }
}

// ---------------- embedding build: relu(P[f0]+Q[f1]+b) + squared norm ----------------
__global__ void k_embed(const float* __restrict__ bias) {
    int row = blockIdx.x;         // [0, NQT+NST)
    int tid = threadIdx.x;        // 256
    float *dst, *nout;
    int f0, f1;
    if (row < NQT) {
        int n = row / TT, t = row % TT;
        f0 = n * SEQ + c_p0[t];
        f1 = n * SEQ + c_p1[t];
        dst = g_QE + (size_t)row * D; nout = &g_qn[row];
    } else {
        int si = row - NQT;
        int c = si / 225, r = si % 225;
        int s = r / TT, t = r % TT;
        int base = QF + (c * SHOT + s) * SEQ;
        f0 = base + c_p0[t];
        f1 = base + c_p1[t];
        dst = g_SE + (size_t)si * D; nout = &g_sn[si];
    }
    const float4* a0 = (const float4*)(g_EF + (size_t)f0 * 2 * D);        // W0 half of f0
    const float4* a1 = (const float4*)(g_EF + (size_t)f1 * 2 * D + D);    // W1 half of f1
    const float4* bb = (const float4*)bias;
    float4* o4 = (float4*)dst;
    float nrm = 0.f;
    for (int v = tid; v < D / 4; v += 256) {
        float4 x = a0[v], y = a1[v], z = bb[v], r4;
        r4.x = fmaxf(x.x + y.x + z.x, 0.f);
        r4.y = fmaxf(x.y + y.y + z.y, 0.f);
        r4.z = fmaxf(x.z + y.z + z.z, 0.f);
        r4.w = fmaxf(x.w + y.w + z.w, 0.f);
        o4[v] = r4;
        nrm += r4.x * r4.x + r4.y * r4.y + r4.z * r4.z + r4.w * r4.w;
    }
    __shared__ float sred[256];
    sred[tid] = nrm; __syncthreads();
    for (int s = 128; s; s >>= 1) {
        if (tid < s) sred[tid] += sred[tid + s];
        __syncthreads();
    }
    if (tid == 0) *nout = sred[0];
}

// ---------------- per-(class, query-tuple) reductions: rowmax, argmax, ave ----------------
__global__ void k_classred() {
    int w = (blockIdx.x * blockDim.x + threadIdx.x) >> 5;
    int lane = threadIdx.x & 31;
    if (w >= WAY * NQT) return;
    int c = w / NQT, qi = w % NQT;
    const float* row = g_DQ + (size_t)qi * NST + c * 225;
    float best = -1.f; int bidx = 0;
    float g0 = -1.f, g1 = -1.f, g2 = -1.f, g3 = -1.f, g4 = -1.f;
    for (int j = lane; j < 225; j += 32) {
        float v = row[j];
        if (v > best) { best = v; bidx = j; }
        int s = j % 5;   // dist_class reshape: j = t'*5 + s'
        if      (s == 0) g0 = fmaxf(g0, v);
        else if (s == 1) g1 = fmaxf(g1, v);
        else if (s == 2) g2 = fmaxf(g2, v);
        else if (s == 3) g3 = fmaxf(g3, v);
        else             g4 = fmaxf(g4, v);
    }
#pragma unroll
    for (int off = 16; off; off >>= 1) {
        float ob = __shfl_down_sync(0xffffffff, best, off);
        int   oi = __shfl_down_sync(0xffffffff, bidx, off);
        if (ob > best || (ob == best && oi < bidx)) { best = ob; bidx = oi; }
        g0 = fmaxf(g0, __shfl_down_sync(0xffffffff, g0, off));
        g1 = fmaxf(g1, __shfl_down_sync(0xffffffff, g1, off));
        g2 = fmaxf(g2, __shfl_down_sync(0xffffffff, g2, off));
        g3 = fmaxf(g3, __shfl_down_sync(0xffffffff, g3, off));
        g4 = fmaxf(g4, __shfl_down_sync(0xffffffff, g4, off));
    }
    if (lane == 0) {
        g_rowmax[w] = best;
        g_pos[w]    = bidx;
        g_ave[w]    = (g0 + g1 + g2 + g3 + g4) * 0.2f;
    }
}

// ---------------- record accumulation over 3375 query tuples ----------------
__global__ void k_record() {
    int c = blockIdx.y;
    int tid = threadIdx.x;                 // 128
    __shared__ int srec[NST];
    for (int j = tid; j < NST; j += 128) srec[j] = 0;
    __syncthreads();
    int q0 = blockIdx.x * 125;             // 27 chunks * 125 = 3375
    for (int qi = q0; qi < q0 + 125; qi++) {
        int   p = g_pos[c * NQT + qi];
        float a = g_ave[c * NQT + qi];
        const float* row = g_SD + (size_t)(c * 225 + p) * NST;
        for (int j = tid; j < NST; j += 128)
            srec[j] += (row[j] > a) ? 1 : 0;
    }
    __syncthreads();
    for (int j = tid; j < NST; j += 128)
        atomicAdd(&g_record[c * NST + j], srec[j]);
}

// ---------------- threshold + mask + msum per class ----------------
__global__ void k_mask() {
    int c = blockIdx.x;
    int tid = threadIdx.x;                 // 256
    __shared__ float sred[256];
    __shared__ int   snz[256];
    __shared__ float s_thr;
    float msum_acc = 0.f;
    for (int m = 0; m < WAY; m++) {
        if (m == c) {
            if (tid < 225) g_mask[c * NST + m * 225 + tid] = 0.f;
            continue;
        }
        int rec = 0;
        if (tid < 225) rec = g_record[c * NST + m * 225 + tid];
        sred[tid] = (tid < 225) ? (float)rec : 0.f;
        snz[tid]  = (tid < 225 && rec != 0) ? 1 : 0;
        __syncthreads();
        for (int s = 128; s; s >>= 1) {
            if (tid < s) { sred[tid] += sred[tid + s]; snz[tid] += snz[tid + s]; }
            __syncthreads();
        }
        if (tid == 0) s_thr = sred[0] / fmaxf((float)snz[0], 1.f);
        __syncthreads();
        if (tid < 225) {
            float mk = ((float)rec < s_thr) ? 1.f : 0.f;
            g_mask[c * NST + m * 225 + tid] = mk;
            msum_acc += mk;
        }
        __syncthreads();
    }
    sred[tid] = msum_acc; __syncthreads();
    for (int s = 128; s; s >>= 1) {
        if (tid < s) sred[tid] += sred[tid + s];
        __syncthreads();
    }
    if (tid == 0) g_msum[c] = fmaxf(sred[0], 1.f);
}

// ---------------- masked mean over DQ columns -> contrast ----------------
__global__ void k_contrast() {
    int qi = blockIdx.x;
    int tid = threadIdx.x;                 // 128
    const float* row = g_DQ + (size_t)qi * NST;
    float a0 = 0.f, a1 = 0.f, a2 = 0.f, a3 = 0.f, a4 = 0.f;
    for (int j = tid; j < NST; j += 128) {
        float d = row[j];
        a0 += d * g_mask[0 * NST + j];
        a1 += d * g_mask[1 * NST + j];
        a2 += d * g_mask[2 * NST + j];
        a3 += d * g_mask[3 * NST + j];
        a4 += d * g_mask[4 * NST + j];
    }
    __shared__ float red[WAY][128];
    red[0][tid] = a0; red[1][tid] = a1; red[2][tid] = a2;
    red[3][tid] = a3; red[4][tid] = a4;
    __syncthreads();
    for (int s = 64; s; s >>= 1) {
        if (tid < s)
#pragma unroll
            for (int cc = 0; cc < WAY; cc++) red[cc][tid] += red[cc][tid + s];
        __syncthreads();
    }
    if (tid < WAY) {
        float val = red[tid][0] / g_msum[tid] * (1.f / (4.f * 45.f));
        atomicAdd(&g_contrast[(qi / TT) * WAY + tid], val);
    }
}

// ---------------- final outputs ----------------
__global__ void k_final(float* __restrict__ out, int out_size) {
    int idx = blockIdx.x * blockDim.x + threadIdx.x;
    if (idx >= NQ * WAY) return;
    int n = idx / WAY, c = idx % WAY;
    float s = 0.f;
    for (int t = 0; t < TT; t++) s += g_rowmax[c * NQT + n * TT + t];
    float dm = s * (1.f / 45.f);
    float ct = g_contrast[idx];
    float lg = dm / (ct + dm);
    if (idx < out_size) out[idx] = dm;
    if (NQ * WAY + idx < out_size) out[NQ * WAY + idx] = lg;
}

// ---------------- launch ----------------
extern "C" void kernel_launch(void* const* d_in, const int* in_sizes, int n_in,
                              void* d_out, int out_size) {
    const float* support = (const float*)d_in[0];   // [25,10,2048]
    const float* queries = (const float*)d_in[2];   // [75,10,2048]
    const float* W       = (const float*)d_in[3];   // [2048,4096]
    const float* bias    = (const float*)d_in[4];   // [2048]
    float* out = (float*)d_out;

    float *EF, *QE, *SE, *qn, *sn, *DQ, *SD;
    cudaGetSymbolAddress((void**)&EF, g_EF);
    cudaGetSymbolAddress((void**)&QE, g_QE);
    cudaGetSymbolAddress((void**)&SE, g_SE);
    cudaGetSymbolAddress((void**)&qn, g_qn);
    cudaGetSymbolAddress((void**)&sn, g_sn);
    cudaGetSymbolAddress((void**)&DQ, g_DQ);
    cudaGetSymbolAddress((void**)&SD, g_SD);

    k_init<<<22, 256>>>();

    // Fused per-frame projection: [1000 frames, 4096 outs] = frames @ [W0;W1]^T
    sgemm_nt<2><<<dim3(32, 8), 256>>>(queries, support, W, EF,
                                      NF, 2 * D, D, 0, 0, 2 * D, nullptr, nullptr);

    k_embed<<<NQT + NST, 256>>>(bias);

    // distance matrices (GEMM + sqrt epilogue)
    sgemm_nt<1><<<dim3(9, 27), 256>>>(QE, nullptr, SE, DQ, NQT, NST, D, D, D, NST, qn, sn);
    sgemm_nt<1><<<dim3(9, 9),  256>>>(SE, nullptr, SE, SD, NST, NST, D, D, D, NST, sn, sn);

    k_classred<<<2110, 256>>>();
    k_record<<<dim3(27, WAY), 128>>>();
    k_mask<<<WAY, 256>>>();
    k_contrast<<<NQT, 128>>>();
    k_final<<<2, 256>>>(out, out_size);
}

// round 3
// speedup vs baseline: 1.6963x; 1.0922x over previous
#include <cuda_runtime.h>
#include <math.h>

// ---------------- problem constants ----------------
#define SEQ   10
#define WAY   5
#define SHOT  5
#define TT    45          // C(10,2)
#define D     2048        // OUT_DIM == IN_DIM
#define NQ    75
#define NS    25
#define NQT   3375        // NQ*TT
#define NST   1125        // NS*TT
#define QF    750         // NQ*SEQ query frames
#define SF    250         // NS*SEQ support frames
#define NF    1000        // total frames

// itertools.combinations(range(10), 2) order
__constant__ int c_p0[TT] = {0,0,0,0,0,0,0,0,0, 1,1,1,1,1,1,1,1, 2,2,2,2,2,2,2,
                             3,3,3,3,3,3, 4,4,4,4,4, 5,5,5,5, 6,6,6, 7,7, 8};
__constant__ int c_p1[TT] = {1,2,3,4,5,6,7,8,9, 2,3,4,5,6,7,8,9, 3,4,5,6,7,8,9,
                             4,5,6,7,8,9, 5,6,7,8,9, 6,7,8,9, 7,8,9, 8,9, 9};

// ---------------- scratch (static device memory; no runtime allocs) ----------------
__device__ float g_EF[NF * 2 * D];    // per-frame projections: [frame][0:2048]=W0 half, [2048:4096]=W1 half
__device__ float g_QE[NQT * D];       // q_embed
__device__ float g_SE[NST * D];       // support_all flattened [c*225 + s*45 + t]
__device__ float g_qn[NQT];           // squared norms
__device__ float g_sn[NST];
__device__ float g_DQ[NQT * NST];     // cdist(q_embed, support_all)
__device__ float g_SD[NST * NST];     // cdist(support_all, support_all)
__device__ float g_rowmax[WAY * NQT];
__device__ int   g_pos[WAY * NQT];
__device__ float g_ave[WAY * NQT];
__device__ int   g_record[WAY * NST];
__device__ float g_mask[WAY * NST];
__device__ float g_msum[WAY];
__device__ float g_contrast[NQ * WAY];

typedef unsigned long long u64;

__device__ __forceinline__ u64 pk(float lo, float hi) {
    u64 r; asm("mov.b64 %0, {%1, %2};" : "=l"(r) : "f"(lo), "f"(hi)); return r;
}
__device__ __forceinline__ void ffma2(u64& d, u64 a, u64 b) {
    asm("fma.rn.f32x2 %0, %1, %2, %0;" : "+l"(d) : "l"(a), "l"(b));
}
__device__ __forceinline__ float2 upk(u64 v) {
    float2 f; asm("mov.b64 {%0, %1}, %2;" : "=f"(f.x), "=f"(f.y) : "l"(v)); return f;
}

// ---------------- init ----------------
__global__ void k_init() {
    int i = blockIdx.x * blockDim.x + threadIdx.x;
    if (i < WAY * NST) g_record[i] = 0;
    if (i < NQ * WAY)  g_contrast[i] = 0.f;
}

// ---------------- NT SGEMM, FFMA2 core, double-buffered pipeline ----------------
// MODE 1: merged distance GEMMs. blockIdx.y<27 -> DQ rows (A=g_QE), else SD rows (A=g_SE).
//         B = g_SE. Epilogue C = sqrt(max(an[r]+bn[c]-2*acc, 0)).
// MODE 2: embedding GEMM: A rows 0..749 queries, 750.. support;
//         B row n -> W + (n&2047)*4096 + (n&2048); plain store to C.
#define BM 128
#define BN 128
#define BK 16

template<int MODE>
__global__ void __launch_bounds__(256, 2) sgemm_nt(
    const float* __restrict__ Aq, const float* __restrict__ As_,
    const float* __restrict__ B, float* __restrict__ Cg,
    int M, int N, int K, int ldc)
{
    __shared__ float Ash[2][BK][BM];
    __shared__ float Bsh[2][BK][BN];
    int tid = threadIdx.x;
    int tx = tid & 15, ty = tid >> 4;

    int n0 = blockIdx.x * BN;
    int m0;
    const float* anp = nullptr; const float* bnp = nullptr;
    float* C = Cg;
    int Mloc = M;
    const float* Abase = Aq;
    if (MODE == 1) {
        int y = blockIdx.y;
        if (y < 27) { m0 = y * BM;        Abase = g_QE; anp = g_qn; C = g_DQ; Mloc = NQT; }
        else        { m0 = (y - 27) * BM; Abase = g_SE; anp = g_sn; C = g_SD; Mloc = NST; }
        bnp = g_sn;
    } else {
        m0 = blockIdx.y * BM;
    }

    // per-thread loader descriptors: 2 slots, each = one float4 of A + one of B
    const float* aptr[2]; const float* bptr[2];
    int ldrow[2], ldk4[2];
#pragma unroll
    for (int i = 0; i < 2; i++) {
        int e = tid + i * 256;            // [0,512)
        int row = e >> 2; int k4 = (e & 3) * 4;
        ldrow[i] = row; ldk4[i] = k4;
        int r = m0 + row;
        int rc = (r < Mloc) ? r : 0;      // clamp: garbage rows never stored
        if (MODE == 2) aptr[i] = (rc < QF) ? (Aq + (size_t)rc * D + k4)
                                           : (As_ + (size_t)(rc - QF) * D + k4);
        else           aptr[i] = Abase + (size_t)rc * D + k4;
        int nr = n0 + row;
        int nc = (nr < N) ? nr : 0;
        if (MODE == 2) bptr[i] = B + (size_t)(nc & 2047) * 4096 + (nc & 2048) + k4;
        else           bptr[i] = g_SE + (size_t)nc * D + k4;
    }

    u64 acc2[8][4];
#pragma unroll
    for (int i = 0; i < 8; i++)
#pragma unroll
        for (int j = 0; j < 4; j++) acc2[i][j] = 0ull;

    const int T = K / BK;
    float4 pa[2], pb[2];
#pragma unroll
    for (int i = 0; i < 2; i++) {
        pa[i] = *(const float4*)(aptr[i]);
        pb[i] = *(const float4*)(bptr[i]);
    }

    for (int t = 0; t < T; t++) {
        int buf = t & 1;
        // STS tile t (writes target the buffer last read at t-1; its readers passed
        // the sync at end of t-1, so one sync per tile is sufficient)
#pragma unroll
        for (int i = 0; i < 2; i++) {
            int row = ldrow[i], k4 = ldk4[i];
            Ash[buf][k4 + 0][row] = pa[i].x; Ash[buf][k4 + 1][row] = pa[i].y;
            Ash[buf][k4 + 2][row] = pa[i].z; Ash[buf][k4 + 3][row] = pa[i].w;
            Bsh[buf][k4 + 0][row] = pb[i].x; Bsh[buf][k4 + 1][row] = pb[i].y;
            Bsh[buf][k4 + 2][row] = pb[i].z; Bsh[buf][k4 + 3][row] = pb[i].w;
        }
        __syncthreads();
        if (t + 1 < T) {
            int kk = (t + 1) * BK;
#pragma unroll
            for (int i = 0; i < 2; i++) {
                pa[i] = *(const float4*)(aptr[i] + kk);
                pb[i] = *(const float4*)(bptr[i] + kk);
            }
        }
#pragma unroll
        for (int k = 0; k < BK; k++) {
            float4 a0 = *(const float4*)&Ash[buf][k][ty * 4];
            float4 a1 = *(const float4*)&Ash[buf][k][64 + ty * 4];
            u64 aa[8];
            aa[0] = pk(a0.x, a0.x); aa[1] = pk(a0.y, a0.y);
            aa[2] = pk(a0.z, a0.z); aa[3] = pk(a0.w, a0.w);
            aa[4] = pk(a1.x, a1.x); aa[5] = pk(a1.y, a1.y);
            aa[6] = pk(a1.z, a1.z); aa[7] = pk(a1.w, a1.w);
            const u64* bp0 = (const u64*)&Bsh[buf][k][tx * 4];
            const u64* bp1 = (const u64*)&Bsh[buf][k][64 + tx * 4];
            u64 b2[4];
            b2[0] = bp0[0]; b2[1] = bp0[1];
            b2[2] = bp1[0]; b2[3] = bp1[1];
#pragma unroll
            for (int i = 0; i < 8; i++)
#pragma unroll
                for (int j = 0; j < 4; j++) ffma2(acc2[i][j], aa[i], b2[j]);
        }
        __syncthreads();
    }

#pragma unroll
    for (int i = 0; i < 8; i++) {
        int r = m0 + ((i < 4) ? (ty * 4 + i) : (64 + ty * 4 + i - 4));
        if (r >= Mloc) continue;
        float anr = (MODE == 1) ? anp[r] : 0.f;
#pragma unroll
        for (int j = 0; j < 4; j++) {
            int cc = n0 + ((j < 2) ? (tx * 4 + j * 2) : (64 + tx * 4 + (j - 2) * 2));
            float2 v2 = upk(acc2[i][j]);
            float v0 = v2.x, v1 = v2.y;
            if (MODE == 1) {
                if (cc < N)     v0 = sqrtf(fmaxf(anr + bnp[cc]     - 2.f * v0, 0.f));
                if (cc + 1 < N) v1 = sqrtf(fmaxf(anr + bnp[cc + 1] - 2.f * v1, 0.f));
            }
            if (cc < N)     C[(size_t)r * ldc + cc]     = v0;
            if (cc + 1 < N) C[(size_t)r * ldc + cc + 1] = v1;
        }
    }
}

// ---------------- embedding build: relu(P[f0]+Q[f1]+b) + squared norm ----------------
__global__ void k_embed(const float* __restrict__ bias) {
    int row = blockIdx.x;         // [0, NQT+NST)
    int tid = threadIdx.x;        // 256
    float *dst, *nout;
    int f0, f1;
    if (row < NQT) {
        int n = row / TT, t = row % TT;
        f0 = n * SEQ + c_p0[t];
        f1 = n * SEQ + c_p1[t];
        dst = g_QE + (size_t)row * D; nout = &g_qn[row];
    } else {
        int si = row - NQT;
        int c = si / 225, r = si % 225;
        int s = r / TT, t = r % TT;
        int base = QF + (c * SHOT + s) * SEQ;
        f0 = base + c_p0[t];
        f1 = base + c_p1[t];
        dst = g_SE + (size_t)si * D; nout = &g_sn[si];
    }
    const float4* a0 = (const float4*)(g_EF + (size_t)f0 * 2 * D);        // W0 half of f0
    const float4* a1 = (const float4*)(g_EF + (size_t)f1 * 2 * D + D);    // W1 half of f1
    const float4* bb = (const float4*)bias;
    float4* o4 = (float4*)dst;
    float nrm = 0.f;
    for (int v = tid; v < D / 4; v += 256) {
        float4 x = a0[v], y = a1[v], z = bb[v], r4;
        r4.x = fmaxf(x.x + y.x + z.x, 0.f);
        r4.y = fmaxf(x.y + y.y + z.y, 0.f);
        r4.z = fmaxf(x.z + y.z + z.z, 0.f);
        r4.w = fmaxf(x.w + y.w + z.w, 0.f);
        o4[v] = r4;
        nrm += r4.x * r4.x + r4.y * r4.y + r4.z * r4.z + r4.w * r4.w;
    }
    __shared__ float sred[256];
    sred[tid] = nrm; __syncthreads();
    for (int s = 128; s; s >>= 1) {
        if (tid < s) sred[tid] += sred[tid + s];
        __syncthreads();
    }
    if (tid == 0) *nout = sred[0];
}

// ---------------- per-(class, query-tuple) reductions: rowmax, argmax, ave ----------------
__global__ void k_classred() {
    int w = (blockIdx.x * blockDim.x + threadIdx.x) >> 5;
    int lane = threadIdx.x & 31;
    if (w >= WAY * NQT) return;
    int c = w / NQT, qi = w % NQT;
    const float* row = g_DQ + (size_t)qi * NST + c * 225;
    float best = -1.f; int bidx = 0;
    float g0 = -1.f, g1 = -1.f, g2 = -1.f, g3 = -1.f, g4 = -1.f;
    for (int j = lane; j < 225; j += 32) {
        float v = row[j];
        if (v > best) { best = v; bidx = j; }
        int s = j % 5;   // dist_class reshape: j = t'*5 + s'
        if      (s == 0) g0 = fmaxf(g0, v);
        else if (s == 1) g1 = fmaxf(g1, v);
        else if (s == 2) g2 = fmaxf(g2, v);
        else if (s == 3) g3 = fmaxf(g3, v);
        else             g4 = fmaxf(g4, v);
    }
#pragma unroll
    for (int off = 16; off; off >>= 1) {
        float ob = __shfl_down_sync(0xffffffff, best, off);
        int   oi = __shfl_down_sync(0xffffffff, bidx, off);
        if (ob > best || (ob == best && oi < bidx)) { best = ob; bidx = oi; }
        g0 = fmaxf(g0, __shfl_down_sync(0xffffffff, g0, off));
        g1 = fmaxf(g1, __shfl_down_sync(0xffffffff, g1, off));
        g2 = fmaxf(g2, __shfl_down_sync(0xffffffff, g2, off));
        g3 = fmaxf(g3, __shfl_down_sync(0xffffffff, g3, off));
        g4 = fmaxf(g4, __shfl_down_sync(0xffffffff, g4, off));
    }
    if (lane == 0) {
        g_rowmax[w] = best;
        g_pos[w]    = bidx;
        g_ave[w]    = (g0 + g1 + g2 + g3 + g4) * 0.2f;
    }
}

// ---------------- record accumulation over 3375 query tuples ----------------
__global__ void k_record() {
    int c = blockIdx.y;
    int tid = threadIdx.x;                 // 128
    __shared__ int srec[NST];
    for (int j = tid; j < NST; j += 128) srec[j] = 0;
    __syncthreads();
    int q0 = blockIdx.x * 125;             // 27 chunks * 125 = 3375
    for (int qi = q0; qi < q0 + 125; qi++) {
        int   p = g_pos[c * NQT + qi];
        float a = g_ave[c * NQT + qi];
        const float* row = g_SD + (size_t)(c * 225 + p) * NST;
        for (int j = tid; j < NST; j += 128)
            srec[j] += (row[j] > a) ? 1 : 0;
    }
    __syncthreads();
    for (int j = tid; j < NST; j += 128)
        atomicAdd(&g_record[c * NST + j], srec[j]);
}

// ---------------- threshold + mask + msum per class ----------------
__global__ void k_mask() {
    int c = blockIdx.x;
    int tid = threadIdx.x;                 // 256
    __shared__ float sred[256];
    __shared__ int   snz[256];
    __shared__ float s_thr;
    float msum_acc = 0.f;
    for (int m = 0; m < WAY; m++) {
        if (m == c) {
            if (tid < 225) g_mask[c * NST + m * 225 + tid] = 0.f;
            continue;
        }
        int rec = 0;
        if (tid < 225) rec = g_record[c * NST + m * 225 + tid];
        sred[tid] = (tid < 225) ? (float)rec : 0.f;
        snz[tid]  = (tid < 225 && rec != 0) ? 1 : 0;
        __syncthreads();
        for (int s = 128; s; s >>= 1) {
            if (tid < s) { sred[tid] += sred[tid + s]; snz[tid] += snz[tid + s]; }
            __syncthreads();
        }
        if (tid == 0) s_thr = sred[0] / fmaxf((float)snz[0], 1.f);
        __syncthreads();
        if (tid < 225) {
            float mk = ((float)rec < s_thr) ? 1.f : 0.f;
            g_mask[c * NST + m * 225 + tid] = mk;
            msum_acc += mk;
        }
        __syncthreads();
    }
    sred[tid] = msum_acc; __syncthreads();
    for (int s = 128; s; s >>= 1) {
        if (tid < s) sred[tid] += sred[tid + s];
        __syncthreads();
    }
    if (tid == 0) g_msum[c] = fmaxf(sred[0], 1.f);
}

// ---------------- masked mean over DQ columns -> contrast ----------------
__global__ void k_contrast() {
    int qi = blockIdx.x;
    int tid = threadIdx.x;                 // 128
    const float* row = g_DQ + (size_t)qi * NST;
    float a0 = 0.f, a1 = 0.f, a2 = 0.f, a3 = 0.f, a4 = 0.f;
    for (int j = tid; j < NST; j += 128) {
        float d = row[j];
        a0 += d * g_mask[0 * NST + j];
        a1 += d * g_mask[1 * NST + j];
        a2 += d * g_mask[2 * NST + j];
        a3 += d * g_mask[3 * NST + j];
        a4 += d * g_mask[4 * NST + j];
    }
    __shared__ float red[WAY][128];
    red[0][tid] = a0; red[1][tid] = a1; red[2][tid] = a2;
    red[3][tid] = a3; red[4][tid] = a4;
    __syncthreads();
    for (int s = 64; s; s >>= 1) {
        if (tid < s)
#pragma unroll
            for (int cc = 0; cc < WAY; cc++) red[cc][tid] += red[cc][tid + s];
        __syncthreads();
    }
    if (tid < WAY) {
        float val = red[tid][0] / g_msum[tid] * (1.f / (4.f * 45.f));
        atomicAdd(&g_contrast[(qi / TT) * WAY + tid], val);
    }
}

// ---------------- final outputs ----------------
__global__ void k_final(float* __restrict__ out, int out_size) {
    int idx = blockIdx.x * blockDim.x + threadIdx.x;
    if (idx >= NQ * WAY) return;
    int n = idx / WAY, c = idx % WAY;
    float s = 0.f;
    for (int t = 0; t < TT; t++) s += g_rowmax[c * NQT + n * TT + t];
    float dm = s * (1.f / 45.f);
    float ct = g_contrast[idx];
    float lg = dm / (ct + dm);
    if (idx < out_size) out[idx] = dm;
    if (NQ * WAY + idx < out_size) out[NQ * WAY + idx] = lg;
}

// ---------------- launch ----------------
extern "C" void kernel_launch(void* const* d_in, const int* in_sizes, int n_in,
                              void* d_out, int out_size) {
    const float* support = (const float*)d_in[0];   // [25,10,2048]
    const float* queries = (const float*)d_in[2];   // [75,10,2048]
    const float* W       = (const float*)d_in[3];   // [2048,4096]
    const float* bias    = (const float*)d_in[4];   // [2048]
    float* out = (float*)d_out;

    float* EF;
    cudaGetSymbolAddress((void**)&EF, g_EF);

    k_init<<<22, 256>>>();

    // Fused per-frame projection: [1000 frames, 4096 outs] = frames @ [W0;W1]^T
    sgemm_nt<2><<<dim3(32, 8), 256>>>(queries, support, W, EF,
                                      NF, 2 * D, D, 2 * D);

    k_embed<<<NQT + NST, 256>>>(bias);

    // merged distance GEMMs: y<27 -> DQ tiles, y>=27 -> SD tiles (one wave, 324 CTAs)
    sgemm_nt<1><<<dim3(9, 36), 256>>>(nullptr, nullptr, nullptr, nullptr,
                                      0, NST, D, NST);

    k_classred<<<2110, 256>>>();
    k_record<<<dim3(27, WAY), 128>>>();
    k_mask<<<WAY, 256>>>();
    k_contrast<<<NQT, 128>>>();
    k_final<<<2, 256>>>(out, out_size);
}